// round 16
// baseline (speedup 1.0000x reference)
#include <cuda_runtime.h>
#include <cuda_bf16.h>
#include <math.h>
#include <stdint.h>

#define NROWS 4096
#define KDIM  1024
#define NHEAD 2002
#define CUT0  2000
#define CUT1  10000
#define NTOK  50257
#define SZ0   8000
#define SZ1   40257
#define D0    256
#define D1    64
#define LOG2E 1.4426950408889634f

// ---------------- scratch (device globals; no allocation allowed) -----------
__device__ float g_proj0[NROWS * D0];
__device__ float g_proj1[NROWS * D1];
__device__ float g_sum_head[NROWS];
__device__ float g_sum_tail[NROWS];
__device__ int   g_idx0[NROWS];
__device__ int   g_idx1[NROWS];
__device__ int   g_cnt0, g_cnt1;

__device__ __align__(16) __nv_bfloat16 g_inh[NROWS * KDIM];
__device__ __align__(16) __nv_bfloat16 g_headWh[NHEAD * KDIM];   // pre-scaled by log2e
__device__ __align__(16) __nv_bfloat16 g_emb0h[SZ0 * D0];        // pre-scaled by log2e
__device__ __align__(16) __nv_bfloat16 g_emb1h[SZ1 * D1];        // pre-scaled by log2e
__device__ __align__(16) __nv_bfloat16 g_proj0h[NROWS * D0];
__device__ __align__(16) __nv_bfloat16 g_proj1h[NROWS * D1];
__device__ __align__(16) __nv_bfloat16 g_lin0t[D0 * KDIM];
__device__ __align__(16) __nv_bfloat16 g_lin1t[D1 * KDIM];

// ---------------- helpers ----------------------------------------------------
__device__ __forceinline__ void cp16(uint32_t s, const void* g, bool v) {
    if (v) asm volatile("cp.async.cg.shared.global [%0], [%1], 16;\n" :: "r"(s), "l"(g));
    else   asm volatile("cp.async.cg.shared.global [%0], [%1], 16, 0;\n" :: "r"(s), "l"(g));
}
__device__ __forceinline__ void cpcommit() { asm volatile("cp.async.commit_group;\n"); }
template<int N> __device__ __forceinline__ void cpwait() {
    asm volatile("cp.async.wait_group %0;\n" :: "n"(N));
}
__device__ __forceinline__ void mma_bf16(float c[4], const uint32_t a[4], const uint32_t b[2]) {
    asm volatile(
        "mma.sync.aligned.m16n8k16.row.col.f32.bf16.bf16.f32 "
        "{%0,%1,%2,%3}, {%4,%5,%6,%7}, {%8,%9}, {%0,%1,%2,%3};"
        : "+f"(c[0]), "+f"(c[1]), "+f"(c[2]), "+f"(c[3])
        : "r"(a[0]), "r"(a[1]), "r"(a[2]), "r"(a[3]), "r"(b[0]), "r"(b[1]));
}
__device__ __forceinline__ void ldsm4(uint32_t r[4], uint32_t addr) {
    asm volatile("ldmatrix.sync.aligned.m8n8.x4.shared.b16 {%0,%1,%2,%3}, [%4];"
        : "=r"(r[0]), "=r"(r[1]), "=r"(r[2]), "=r"(r[3]) : "r"(addr));
}
__device__ __forceinline__ float ex2f(float x) {
    float r; asm("ex2.approx.f32 %0, %1;" : "=f"(r) : "f"(x)); return r;
}

// ---------------- prep: classify + bf16 conversions (weights x log2e) --------
__global__ void prep_kernel(const float* __restrict__ i0, const float* __restrict__ i1,
                            const float* __restrict__ i2, const float* __restrict__ i3,
                            const float* __restrict__ lin0, const float* __restrict__ lin1,
                            const int* __restrict__ targets) {
    int t = blockIdx.x * blockDim.x + threadIdx.x;
    int gs = gridDim.x * blockDim.x;
    for (int i = t; i < NROWS; i += gs) {
        int tg = targets[i];
        if (tg >= CUT0 && tg < CUT1) { int p = atomicAdd(&g_cnt0, 1); g_idx0[p] = i; }
        else if (tg >= CUT1)         { int p = atomicAdd(&g_cnt1, 1); g_idx1[p] = i; }
    }
    const float* srcs[4] = { i0, i1, i2, i3 };
    __nv_bfloat16* dsts[4] = { g_inh, g_headWh, g_emb0h, g_emb1h };
    const int n4s[4] = { NROWS * KDIM / 4, NHEAD * KDIM / 4, SZ0 * D0 / 4, SZ1 * D1 / 4 };
    #pragma unroll
    for (int a = 0; a < 4; a++) {
        float sc = (a == 0) ? 1.f : LOG2E;
        const float4* s = (const float4*)srcs[a];
        __nv_bfloat162* d = (__nv_bfloat162*)dsts[a];
        for (int i = t; i < n4s[a]; i += gs) {
            float4 v = s[i];
            d[2 * i]     = __floats2bfloat162_rn(v.x * sc, v.y * sc);
            d[2 * i + 1] = __floats2bfloat162_rn(v.z * sc, v.w * sc);
        }
    }
    for (int i = t; i < D0 * KDIM; i += gs) {
        int n = i >> 10, k = i & (KDIM - 1);
        g_lin0t[i] = __float2bfloat16(lin0[k * D0 + n]);
    }
    for (int i = t; i < D1 * KDIM; i += gs) {
        int n = i >> 10, k = i & (KDIM - 1);
        g_lin1t[i] = __float2bfloat16(lin1[k * D1 + n]);
    }
}

// ---------------- tensor-core projection (unchanged, proven) -----------------
template<int NOUT, int NBLK, int WHICH>
__device__ __forceinline__ void proj_body(uint32_t* sm, int yIdx) {
    const int AST = 20;
    const int NJ = NBLK / 16;
    uint32_t smB = (uint32_t)__cvta_generic_to_shared(sm);
    const uint32_t aOff[2] = { 0u, 2560u * 4 };
    const uint32_t bOff[2] = { 5120u * 4, (5120u + NBLK * AST) * 4 };

    float* __restrict__ P = (WHICH == 0) ? g_proj0 : g_proj1;
    __nv_bfloat16* __restrict__ Ph = (WHICH == 0) ? g_proj0h : g_proj1h;
    const __nv_bfloat16* __restrict__ Bt = (WHICH == 0) ? g_lin0t : g_lin1t;

    int tid = threadIdx.x;
    int row0 = blockIdx.x * 128;
    int nc = yIdx * NBLK;
    int warp = tid >> 5, lane = tid & 31, grp = lane >> 2, qid = lane & 3;
    int wm = (warp >> 1) * 32, wn = (warp & 1) * (NBLK / 2);

    int ar = tid >> 1, aSeg = (tid & 1) * 32;
    const char* aG = (const char*)(g_inh + (size_t)(row0 + ar) * KDIM) + aSeg;
    const int TPR = 256 / NBLK;
    const int SEG = 64 / TPR;
    int bRow = tid / TPR, bSeg = (tid % TPR) * SEG;
    const char* bG = (const char*)(Bt + (size_t)(nc + bRow) * KDIM) + bSeg;

    uint32_t aLd = (uint32_t)((wm + (lane & 15)) * AST + (lane >> 4) * 4) * 4;
    uint32_t bLd = (uint32_t)((wn + ((lane >> 4) & 1) * 8 + (lane & 7)) * AST
                              + ((lane >> 3) & 1) * 4) * 4;

    float c[2][NJ][4];
    #pragma unroll
    for (int mi = 0; mi < 2; mi++)
        #pragma unroll
        for (int nj = 0; nj < NJ; nj++)
            #pragma unroll
            for (int r = 0; r < 4; r++) c[mi][nj][r] = 0.f;

    {
        uint32_t as = smB + aOff[0] + (uint32_t)(ar * AST) * 4 + aSeg;
        cp16(as, aG, true); cp16(as + 16, aG + 16, true);
        uint32_t bs = smB + bOff[0] + (uint32_t)(bRow * AST) * 4 + bSeg;
        #pragma unroll
        for (int s = 0; s < SEG / 16; s++) cp16(bs + s * 16, bG + s * 16, true);
        cpcommit();
    }
    const int NCH = KDIM / 32;
    for (int ch = 0; ch < NCH; ch++) {
        int cur = ch & 1;
        if (ch + 1 < NCH) {
            int nb = cur ^ 1;
            uint32_t as = smB + aOff[nb] + (uint32_t)(ar * AST) * 4 + aSeg;
            const char* ag = aG + (ch + 1) * 64;
            cp16(as, ag, true); cp16(as + 16, ag + 16, true);
            uint32_t bs = smB + bOff[nb] + (uint32_t)(bRow * AST) * 4 + bSeg;
            const char* bg = bG + (ch + 1) * 64;
            #pragma unroll
            for (int s = 0; s < SEG / 16; s++) cp16(bs + s * 16, bg + s * 16, true);
            cpcommit(); cpwait<1>();
        } else cpwait<0>();
        __syncthreads();
        uint32_t aT = smB + aOff[cur] + aLd;
        uint32_t bT = smB + bOff[cur] + bLd;
        #pragma unroll
        for (int ks = 0; ks < 2; ks++) {
            uint32_t a[2][4], b[NJ][2];
            #pragma unroll
            for (int mi = 0; mi < 2; mi++)
                ldsm4(a[mi], aT + (uint32_t)(mi * 16 * AST + ks * 8) * 4);
            #pragma unroll
            for (int p = 0; p < NJ / 2; p++) {
                uint32_t r[4];
                ldsm4(r, bT + (uint32_t)(p * 16 * AST + ks * 8) * 4);
                b[2 * p][0] = r[0]; b[2 * p][1] = r[1];
                b[2 * p + 1][0] = r[2]; b[2 * p + 1][1] = r[3];
            }
            #pragma unroll
            for (int mi = 0; mi < 2; mi++)
                #pragma unroll
                for (int nj = 0; nj < NJ; nj++)
                    mma_bf16(c[mi][nj], a[mi], b[nj]);
        }
        __syncthreads();
    }
    #pragma unroll
    for (int mi = 0; mi < 2; mi++) {
        #pragma unroll
        for (int nj = 0; nj < NJ; nj++) {
            int r0 = row0 + wm + mi * 16 + grp;
            int col = nc + wn + nj * 8 + 2 * qid;
            long o0 = (long)r0 * NOUT + col;
            long o1 = (long)(r0 + 8) * NOUT + col;
            *reinterpret_cast<float2*>(&P[o0]) = make_float2(c[mi][nj][0], c[mi][nj][1]);
            *reinterpret_cast<float2*>(&P[o1]) = make_float2(c[mi][nj][2], c[mi][nj][3]);
            *reinterpret_cast<__nv_bfloat162*>(&Ph[o0]) =
                __floats2bfloat162_rn(c[mi][nj][0], c[mi][nj][1]);
            *reinterpret_cast<__nv_bfloat162*>(&Ph[o1]) =
                __floats2bfloat162_rn(c[mi][nj][2], c[mi][nj][3]);
        }
    }
}

__global__ void __launch_bounds__(256) proj_all() {
    extern __shared__ uint32_t smp[];
    if (blockIdx.y < 2) proj_body<D0, 128, 0>(smp, blockIdx.y);
    else                proj_body<D1, 64, 1>(smp, 0);
}

// ====== exp-sum: 3-stage pipeline, register row-accumulation, ex2 ============
// chunked: 3 stages of (A 5120 + B 1280) u32 = 19200; rowAcc @19200 (256)
// tail1 resident: A 9216 | 3 x B 2304 @9216 | rowAcc @16128
#define SM_EXP_U32 19456

// ---- chunked body (MODE 0: head, MODE 1: tail0); CH=32, tiles flattened -----
template<int K, int MODE, int NUMY, int NTILES>
__device__ __forceinline__ void chunked_body(uint32_t* sm, int yIdx) {
    const int ST = 20, NCH = K / 32, TOT = NTILES * NCH;
    float* rowAcc = (float*)(sm + 19200);
    uint32_t smB = (uint32_t)__cvta_generic_to_shared(sm);

    int M, ncols;
    const __nv_bfloat16 *Asrc, *Bsrc;
    float* sums;
    if (MODE == 0) { M = NROWS; ncols = NHEAD; Asrc = g_inh;    Bsrc = g_headWh; sums = g_sum_head; }
    else           { M = g_cnt0; ncols = SZ0;  Asrc = g_proj0h; Bsrc = g_emb0h;  sums = g_sum_tail; }

    int row0 = blockIdx.x * 256;
    if (row0 >= M) return;
    int tid = threadIdx.x;
    int rid = row0 + tid; if (rid > M - 1) rid = M - 1;
    int myRow = (MODE == 0) ? rid : g_idx0[rid];
    rowAcc[tid] = 0.f;

    int warp = tid >> 5, lane = tid & 31, grp = lane >> 2, qid = lane & 3;
    int wm = (warp >> 1) * 64, wn = (warp & 1) * 32;

    const char* aG = (const char*)(Asrc + (size_t)myRow * K);
    int bRow = tid >> 2, bSeg = (tid & 3) * 16;

    uint32_t aLd = (uint32_t)((wm + (lane & 15)) * ST + (lane >> 4) * 4) * 4;
    uint32_t bLd = (uint32_t)((wn + ((lane >> 4) & 1) * 8 + (lane & 7)) * ST
                              + ((lane >> 3) & 1) * 4) * 4;

    auto issueC = [&](int c) {
        int t = c / NCH, ch = c - t * NCH;
        int nc = (yIdx + t * NUMY) * 64;
        uint32_t base = smB + (uint32_t)((c % 3) * 6400) * 4;
        uint32_t as = base + (uint32_t)tid * ST * 4;
        const char* ag = aG + ch * 64;
        #pragma unroll
        for (int s = 0; s < 4; s++) cp16(as + s * 16, ag + s * 16, true);
        int bRowG = nc + bRow;
        bool bv = bRowG < ncols;
        const char* bg = (const char*)(Bsrc + (size_t)(bv ? bRowG : 0) * K) + ch * 64 + bSeg;
        cp16(base + (uint32_t)(5120 + bRow * ST) * 4 + bSeg, bg, bv);
    };

    float c[4][4][4];
    float racc[4][2];
    #pragma unroll
    for (int mi = 0; mi < 4; mi++) {
        racc[mi][0] = 0.f; racc[mi][1] = 0.f;
        #pragma unroll
        for (int nj = 0; nj < 4; nj++)
            #pragma unroll
            for (int r = 0; r < 4; r++) c[mi][nj][r] = 0.f;
    }

    issueC(0); cpcommit();
    if (TOT > 1) { issueC(1); cpcommit(); }

    for (int cc = 0; cc < TOT; cc++) {
        if (cc == TOT - 1) cpwait<0>(); else cpwait<1>();
        __syncthreads();
        if (cc + 2 < TOT) { issueC(cc + 2); cpcommit(); }

        uint32_t base = smB + (uint32_t)((cc % 3) * 6400) * 4;
        uint32_t aT = base + aLd;
        uint32_t bT = base + 5120u * 4 + bLd;
        #pragma unroll
        for (int ks = 0; ks < 2; ks++) {
            uint32_t a[4][4], b[4][2];
            #pragma unroll
            for (int mi = 0; mi < 4; mi++)
                ldsm4(a[mi], aT + (uint32_t)(mi * 16 * ST + ks * 8) * 4);
            #pragma unroll
            for (int p = 0; p < 2; p++) {
                uint32_t r[4];
                ldsm4(r, bT + (uint32_t)(p * 16 * ST + ks * 8) * 4);
                b[2 * p][0] = r[0]; b[2 * p][1] = r[1];
                b[2 * p + 1][0] = r[2]; b[2 * p + 1][1] = r[3];
            }
            #pragma unroll
            for (int mi = 0; mi < 4; mi++)
                #pragma unroll
                for (int nj = 0; nj < 4; nj++)
                    mma_bf16(c[mi][nj], a[mi], b[nj]);
        }
        if ((cc + 1) % NCH == 0) {
            int t = cc / NCH;
            int nc = (yIdx + t * NUMY) * 64;
            if (nc + 64 <= ncols) {
                #pragma unroll
                for (int mi = 0; mi < 4; mi++) {
                    float s0 = 0.f, s1 = 0.f;
                    #pragma unroll
                    for (int nj = 0; nj < 4; nj++) {
                        s0 += ex2f(c[mi][nj][0]) + ex2f(c[mi][nj][1]);
                        s1 += ex2f(c[mi][nj][2]) + ex2f(c[mi][nj][3]);
                        c[mi][nj][0] = c[mi][nj][1] = c[mi][nj][2] = c[mi][nj][3] = 0.f;
                    }
                    racc[mi][0] += s0; racc[mi][1] += s1;
                }
            } else {
                #pragma unroll
                for (int mi = 0; mi < 4; mi++) {
                    float s0 = 0.f, s1 = 0.f;
                    #pragma unroll
                    for (int nj = 0; nj < 4; nj++) {
                        int col = nc + wn + nj * 8 + 2 * qid;
                        if (col < ncols)     { s0 += ex2f(c[mi][nj][0]); s1 += ex2f(c[mi][nj][2]); }
                        if (col + 1 < ncols) { s0 += ex2f(c[mi][nj][1]); s1 += ex2f(c[mi][nj][3]); }
                        c[mi][nj][0] = c[mi][nj][1] = c[mi][nj][2] = c[mi][nj][3] = 0.f;
                    }
                    racc[mi][0] += s0; racc[mi][1] += s1;
                }
            }
        }
    }
    // combine: shfl over qid, smem, then one global atomic per row
    #pragma unroll
    for (int mi = 0; mi < 4; mi++) {
        float s0 = racc[mi][0], s1 = racc[mi][1];
        s0 += __shfl_xor_sync(0xffffffffu, s0, 1);
        s0 += __shfl_xor_sync(0xffffffffu, s0, 2);
        s1 += __shfl_xor_sync(0xffffffffu, s1, 1);
        s1 += __shfl_xor_sync(0xffffffffu, s1, 2);
        if (qid == 0) {
            atomicAdd(&rowAcc[wm + mi * 16 + grp], s0);
            atomicAdd(&rowAcc[wm + mi * 16 + grp + 8], s1);
        }
    }
    __syncthreads();
    if (row0 + tid < M) atomicAdd(&sums[myRow], rowAcc[tid]);
}

// ---- tail1: A resident, B 3-stage pipeline over N-tiles ---------------------
template<int NUMY>
__device__ __forceinline__ void tail1_body(uint32_t* sm, int yIdx) {
    const int K = 64, ST = 36, TILES = 630;
    float* rowAcc = (float*)(sm + 16128);
    uint32_t smB = (uint32_t)__cvta_generic_to_shared(sm);

    int M = g_cnt1, ncols = SZ1;
    int row0 = blockIdx.x * 256;
    if (row0 >= M) return;
    int tid = threadIdx.x;
    int rid = row0 + tid; if (rid > M - 1) rid = M - 1;
    int myRow = g_idx1[rid];
    rowAcc[tid] = 0.f;

    int NT = (TILES - yIdx + NUMY - 1) / NUMY;

    {   // resident A (own row) into group 0
        const char* aG = (const char*)(g_proj1h + (size_t)myRow * K);
        uint32_t as = smB + (uint32_t)tid * ST * 4;
        #pragma unroll
        for (int s = 0; s < 8; s++) cp16(as + s * 16, aG + s * 16, true);
    }
    int bRow = tid >> 2, bSeg = (tid & 3) * 32;
    int warp = tid >> 5, lane = tid & 31, grp = lane >> 2, qid = lane & 3;
    int wm = (warp >> 1) * 64, wn = (warp & 1) * 32;

    uint32_t aLd = (uint32_t)((wm + (lane & 15)) * ST + (lane >> 4) * 4) * 4;
    uint32_t bLd = (uint32_t)((wn + ((lane >> 4) & 1) * 8 + (lane & 7)) * ST
                              + ((lane >> 3) & 1) * 4) * 4;

    auto issueT = [&](int c) {
        int nc = (yIdx + c * NUMY) * 64;
        int br = nc + bRow;
        bool v = br < ncols;
        const char* bg = (const char*)(g_emb1h + (size_t)(v ? br : 0) * K) + bSeg;
        uint32_t bs = smB + (uint32_t)((9216 + (c % 3) * 2304) + bRow * ST) * 4 + bSeg;
        cp16(bs, bg, v); cp16(bs + 16, bg + 16, v);
    };

    float racc[4][2];
    #pragma unroll
    for (int mi = 0; mi < 4; mi++) { racc[mi][0] = 0.f; racc[mi][1] = 0.f; }

    issueT(0); cpcommit();
    if (NT > 1) { issueT(1); cpcommit(); }

    for (int cc = 0; cc < NT; cc++) {
        if (cc == NT - 1) cpwait<0>(); else cpwait<1>();
        __syncthreads();
        if (cc + 2 < NT) { issueT(cc + 2); cpcommit(); }

        float c[4][4][4];
        #pragma unroll
        for (int mi = 0; mi < 4; mi++)
            #pragma unroll
            for (int nj = 0; nj < 4; nj++)
                #pragma unroll
                for (int r = 0; r < 4; r++) c[mi][nj][r] = 0.f;

        uint32_t aT = smB + aLd;
        uint32_t bT = smB + (uint32_t)(9216 + (cc % 3) * 2304) * 4 + bLd;
        #pragma unroll
        for (int ks = 0; ks < 4; ks++) {
            uint32_t a[4][4], b[4][2];
            #pragma unroll
            for (int mi = 0; mi < 4; mi++)
                ldsm4(a[mi], aT + (uint32_t)(mi * 16 * ST + ks * 8) * 4);
            #pragma unroll
            for (int p = 0; p < 2; p++) {
                uint32_t r[4];
                ldsm4(r, bT + (uint32_t)(p * 16 * ST + ks * 8) * 4);
                b[2 * p][0] = r[0]; b[2 * p][1] = r[1];
                b[2 * p + 1][0] = r[2]; b[2 * p + 1][1] = r[3];
            }
            #pragma unroll
            for (int mi = 0; mi < 4; mi++)
                #pragma unroll
                for (int nj = 0; nj < 4; nj++)
                    mma_bf16(c[mi][nj], a[mi], b[nj]);
        }
        int nc = (yIdx + cc * NUMY) * 64;
        if (nc + 64 <= ncols) {
            #pragma unroll
            for (int mi = 0; mi < 4; mi++) {
                float s0 = 0.f, s1 = 0.f;
                #pragma unroll
                for (int nj = 0; nj < 4; nj++) {
                    s0 += ex2f(c[mi][nj][0]) + ex2f(c[mi][nj][1]);
                    s1 += ex2f(c[mi][nj][2]) + ex2f(c[mi][nj][3]);
                }
                racc[mi][0] += s0; racc[mi][1] += s1;
            }
        } else {
            #pragma unroll
            for (int mi = 0; mi < 4; mi++) {
                float s0 = 0.f, s1 = 0.f;
                #pragma unroll
                for (int nj = 0; nj < 4; nj++) {
                    int col = nc + wn + nj * 8 + 2 * qid;
                    if (col < ncols)     { s0 += ex2f(c[mi][nj][0]); s1 += ex2f(c[mi][nj][2]); }
                    if (col + 1 < ncols) { s0 += ex2f(c[mi][nj][1]); s1 += ex2f(c[mi][nj][3]); }
                }
                racc[mi][0] += s0; racc[mi][1] += s1;
            }
        }
    }
    #pragma unroll
    for (int mi = 0; mi < 4; mi++) {
        float s0 = racc[mi][0], s1 = racc[mi][1];
        s0 += __shfl_xor_sync(0xffffffffu, s0, 1);
        s0 += __shfl_xor_sync(0xffffffffu, s0, 2);
        s1 += __shfl_xor_sync(0xffffffffu, s1, 1);
        s1 += __shfl_xor_sync(0xffffffffu, s1, 2);
        if (qid == 0) {
            atomicAdd(&rowAcc[wm + mi * 16 + grp], s0);
            atomicAdd(&rowAcc[wm + mi * 16 + grp + 8], s1);
        }
    }
    __syncthreads();
    if (row0 + tid < M) atomicAdd(&g_sum_tail[myRow], rowAcc[tid]);
}

// y-map: [0,8) head (4 tiles each) | [8,28) tail1 | [28,53) tail0 (5 tiles)
__global__ void __launch_bounds__(256, 2) expsum_all() {
    extern __shared__ uint32_t sm[];
    if (blockIdx.y < 8)       chunked_body<KDIM, 0, 8, 4>(sm, blockIdx.y);
    else if (blockIdx.y < 28) tail1_body<20>(sm, blockIdx.y - 8);
    else                      chunked_body<D0, 1, 25, 5>(sm, blockIdx.y - 28);
}

// ---------------- final gather ----------------------------------------------
__global__ void __launch_bounds__(256) final_kernel(
    const float* __restrict__ inputs, const int* __restrict__ targets,
    const float* __restrict__ head_W, const float* __restrict__ emb0,
    const float* __restrict__ emb1, float* __restrict__ out)
{
    int warp = (blockIdx.x * blockDim.x + threadIdx.x) >> 5;
    int lane = threadIdx.x & 31;
    if (warp >= NROWS) return;
    int row = warp;
    int t = targets[row];
    int ht = (t < CUT0) ? t : ((t < CUT1) ? CUT0 : CUT0 + 1);

    float s = 0.f;
    const float* x = inputs + (long)row * KDIM;
    const float* w = head_W + (long)ht * KDIM;
    for (int k = lane; k < KDIM; k += 32) s += x[k] * w[k];
    #pragma unroll
    for (int o = 16; o; o >>= 1) s += __shfl_xor_sync(0xffffffffu, s, o);
    // sums hold 2^(z*log2e) accumulations == exp-space sums
    float res = s - logf(g_sum_head[row]);

    if (t >= CUT0) {
        float tl = 0.f;
        if (t < CUT1) {
            const float* p = g_proj0 + (long)row * D0;
            const float* e = emb0 + (long)(t - CUT0) * D0;
            for (int k = lane; k < D0; k += 32) tl += p[k] * e[k];
        } else {
            const float* p = g_proj1 + (long)row * D1;
            const float* e = emb1 + (long)(t - CUT1) * D1;
            for (int k = lane; k < D1; k += 32) tl += p[k] * e[k];
        }
        #pragma unroll
        for (int o = 16; o; o >>= 1) tl += __shfl_xor_sync(0xffffffffu, tl, o);
        res += tl - logf(g_sum_tail[row]);
    }
    if (lane == 0) out[row] = res;
}

// -------- loss reduction (double) + state reset for next replay ---------------
__global__ void __launch_bounds__(1024) loss_kernel(float* __restrict__ out, int out_size) {
    __shared__ double sh[1024];
    int tid = threadIdx.x;
    double s = 0.0;
    for (int i = tid; i < NROWS; i += 1024) s += (double)out[i];
    sh[tid] = s;
    __syncthreads();
    for (int o = 512; o; o >>= 1) {
        if (tid < o) sh[tid] += sh[tid + o];
        __syncthreads();
    }
    if (tid == 0 && out_size > NROWS)
        out[out_size - 1] = (float)(-sh[0] / (double)NROWS);
    for (int i = tid; i < NROWS; i += 1024) { g_sum_head[i] = 0.f; g_sum_tail[i] = 0.f; }
    if (tid == 0) { g_cnt0 = 0; g_cnt1 = 0; }
}

// ---------------- launch -----------------------------------------------------
extern "C" void kernel_launch(void* const* d_in, const int* in_sizes, int n_in,
                              void* d_out, int out_size) {
    const float* inputs = 0; const int* targets = 0; const float* head_W = 0;
    const float* emb0 = 0; const float* lin0 = 0; const float* emb1 = 0; const float* lin1 = 0;
    for (int i = 0; i < n_in; i++) {
        switch (in_sizes[i]) {
            case NROWS * KDIM:  inputs  = (const float*)d_in[i]; break;
            case NROWS:         targets = (const int*)  d_in[i]; break;
            case NHEAD * KDIM:  head_W  = (const float*)d_in[i]; break;
            case SZ0 * D0:      emb0    = (const float*)d_in[i]; break;
            case KDIM * D0:     lin0    = (const float*)d_in[i]; break;
            case SZ1 * D1:      emb1    = (const float*)d_in[i]; break;
            case KDIM * D1:     lin1    = (const float*)d_in[i]; break;
        }
    }
    float* out = (float*)d_out;

    const int SMEM_PROJ = (2 * 2560 + 2 * 128 * 20) * 4;    // 40 KB
    const int SMEM_EXP  = SM_EXP_U32 * 4;                   // 77.8 KB (2 CTA/SM)
    cudaFuncSetAttribute(proj_all,   cudaFuncAttributeMaxDynamicSharedMemorySize, SMEM_PROJ);
    cudaFuncSetAttribute(expsum_all, cudaFuncAttributeMaxDynamicSharedMemorySize, SMEM_EXP);

    prep_kernel<<<2048, 256>>>(inputs, head_W, emb0, emb1, lin0, lin1, targets);
    proj_all<<<dim3(32, 3), 256, SMEM_PROJ>>>();
    expsum_all<<<dim3(16, 53), 256, SMEM_EXP>>>();
    final_kernel<<<(NROWS * 32) / 256, 256>>>(inputs, targets, head_W, emb0, emb1, out);
    loss_kernel<<<1, 1024>>>(out, out_size);
}

// round 17
// speedup vs baseline: 1.5221x; 1.5221x over previous
#include <cuda_runtime.h>
#include <cuda_bf16.h>
#include <math.h>
#include <stdint.h>

#define NROWS 4096
#define KDIM  1024
#define NHEAD 2002
#define CUT0  2000
#define CUT1  10000
#define NTOK  50257
#define SZ0   8000
#define SZ1   40257
#define D0    256
#define D1    64
#define LOG2E 1.4426950408889634f

// ---------------- scratch (device globals; no allocation allowed) -----------
__device__ float g_proj0[NROWS * D0];
__device__ float g_proj1[NROWS * D1];
__device__ float g_sum_head[NROWS];
__device__ float g_sum_tail[NROWS];
__device__ int   g_idx0[NROWS];
__device__ int   g_idx1[NROWS];
__device__ int   g_cnt0, g_cnt1;

__device__ __align__(16) __nv_bfloat16 g_inh[NROWS * KDIM];
__device__ __align__(16) __nv_bfloat16 g_headWh[NHEAD * KDIM];   // pre-scaled by log2e
__device__ __align__(16) __nv_bfloat16 g_emb0h[SZ0 * D0];        // pre-scaled by log2e
__device__ __align__(16) __nv_bfloat16 g_emb1h[SZ1 * D1];        // pre-scaled by log2e
__device__ __align__(16) __nv_bfloat16 g_proj0h[NROWS * D0];
__device__ __align__(16) __nv_bfloat16 g_proj1h[NROWS * D1];
__device__ __align__(16) __nv_bfloat16 g_lin0t[D0 * KDIM];
__device__ __align__(16) __nv_bfloat16 g_lin1t[D1 * KDIM];

// ---------------- helpers ----------------------------------------------------
__device__ __forceinline__ void cp16(uint32_t s, const void* g, bool v) {
    if (v) asm volatile("cp.async.cg.shared.global [%0], [%1], 16;\n" :: "r"(s), "l"(g));
    else   asm volatile("cp.async.cg.shared.global [%0], [%1], 16, 0;\n" :: "r"(s), "l"(g));
}
__device__ __forceinline__ void cpcommit() { asm volatile("cp.async.commit_group;\n"); }
template<int N> __device__ __forceinline__ void cpwait() {
    asm volatile("cp.async.wait_group %0;\n" :: "n"(N));
}
__device__ __forceinline__ void mma_bf16(float c[4], const uint32_t a[4], const uint32_t b[2]) {
    asm volatile(
        "mma.sync.aligned.m16n8k16.row.col.f32.bf16.bf16.f32 "
        "{%0,%1,%2,%3}, {%4,%5,%6,%7}, {%8,%9}, {%0,%1,%2,%3};"
        : "+f"(c[0]), "+f"(c[1]), "+f"(c[2]), "+f"(c[3])
        : "r"(a[0]), "r"(a[1]), "r"(a[2]), "r"(a[3]), "r"(b[0]), "r"(b[1]));
}
__device__ __forceinline__ void ldsm4(uint32_t r[4], uint32_t addr) {
    asm volatile("ldmatrix.sync.aligned.m8n8.x4.shared.b16 {%0,%1,%2,%3}, [%4];"
        : "=r"(r[0]), "=r"(r[1]), "=r"(r[2]), "=r"(r[3]) : "r"(addr));
}
__device__ __forceinline__ float ex2f(float x) {
    float r; asm("ex2.approx.f32 %0, %1;" : "=f"(r) : "f"(x)); return r;
}

// ---------------- prep: classify + bf16 conversions (weights x log2e) --------
__global__ void prep_kernel(const float* __restrict__ i0, const float* __restrict__ i1,
                            const float* __restrict__ i2, const float* __restrict__ i3,
                            const float* __restrict__ lin0, const float* __restrict__ lin1,
                            const int* __restrict__ targets) {
    int t = blockIdx.x * blockDim.x + threadIdx.x;
    int gs = gridDim.x * blockDim.x;
    for (int i = t; i < NROWS; i += gs) {
        int tg = targets[i];
        if (tg >= CUT0 && tg < CUT1) { int p = atomicAdd(&g_cnt0, 1); g_idx0[p] = i; }
        else if (tg >= CUT1)         { int p = atomicAdd(&g_cnt1, 1); g_idx1[p] = i; }
    }
    const float* srcs[4] = { i0, i1, i2, i3 };
    __nv_bfloat16* dsts[4] = { g_inh, g_headWh, g_emb0h, g_emb1h };
    const int n4s[4] = { NROWS * KDIM / 4, NHEAD * KDIM / 4, SZ0 * D0 / 4, SZ1 * D1 / 4 };
    #pragma unroll
    for (int a = 0; a < 4; a++) {
        float sc = (a == 0) ? 1.f : LOG2E;
        const float4* s = (const float4*)srcs[a];
        __nv_bfloat162* d = (__nv_bfloat162*)dsts[a];
        for (int i = t; i < n4s[a]; i += gs) {
            float4 v = s[i];
            d[2 * i]     = __floats2bfloat162_rn(v.x * sc, v.y * sc);
            d[2 * i + 1] = __floats2bfloat162_rn(v.z * sc, v.w * sc);
        }
    }
    for (int i = t; i < D0 * KDIM; i += gs) {
        int n = i >> 10, k = i & (KDIM - 1);
        g_lin0t[i] = __float2bfloat16(lin0[k * D0 + n]);
    }
    for (int i = t; i < D1 * KDIM; i += gs) {
        int n = i >> 10, k = i & (KDIM - 1);
        g_lin1t[i] = __float2bfloat16(lin1[k * D1 + n]);
    }
}

// ---------------- tensor-core projection (merged, 128-row tiles) -------------
template<int NOUT, int NBLK, int WHICH>
__device__ __forceinline__ void proj_body(uint32_t* sm, int yIdx) {
    const int AST = 20;
    const int NJ = NBLK / 16;
    uint32_t smB = (uint32_t)__cvta_generic_to_shared(sm);
    const uint32_t aOff[2] = { 0u, 2560u * 4 };
    const uint32_t bOff[2] = { 5120u * 4, (5120u + NBLK * AST) * 4 };

    float* __restrict__ P = (WHICH == 0) ? g_proj0 : g_proj1;
    __nv_bfloat16* __restrict__ Ph = (WHICH == 0) ? g_proj0h : g_proj1h;
    const __nv_bfloat16* __restrict__ Bt = (WHICH == 0) ? g_lin0t : g_lin1t;

    int tid = threadIdx.x;
    int row0 = blockIdx.x * 128;
    int nc = yIdx * NBLK;
    int warp = tid >> 5, lane = tid & 31, grp = lane >> 2, qid = lane & 3;
    int wm = (warp >> 1) * 32, wn = (warp & 1) * (NBLK / 2);

    int ar = tid >> 1, aSeg = (tid & 1) * 32;
    const char* aG = (const char*)(g_inh + (size_t)(row0 + ar) * KDIM) + aSeg;
    const int TPR = 256 / NBLK;
    const int SEG = 64 / TPR;
    int bRow = tid / TPR, bSeg = (tid % TPR) * SEG;
    const char* bG = (const char*)(Bt + (size_t)(nc + bRow) * KDIM) + bSeg;

    uint32_t aLd = (uint32_t)((wm + (lane & 15)) * AST + (lane >> 4) * 4) * 4;
    uint32_t bLd = (uint32_t)((wn + ((lane >> 4) & 1) * 8 + (lane & 7)) * AST
                              + ((lane >> 3) & 1) * 4) * 4;

    float c[2][NJ][4];
    #pragma unroll
    for (int mi = 0; mi < 2; mi++)
        #pragma unroll
        for (int nj = 0; nj < NJ; nj++)
            #pragma unroll
            for (int r = 0; r < 4; r++) c[mi][nj][r] = 0.f;

    {
        uint32_t as = smB + aOff[0] + (uint32_t)(ar * AST) * 4 + aSeg;
        cp16(as, aG, true); cp16(as + 16, aG + 16, true);
        uint32_t bs = smB + bOff[0] + (uint32_t)(bRow * AST) * 4 + bSeg;
        #pragma unroll
        for (int s = 0; s < SEG / 16; s++) cp16(bs + s * 16, bG + s * 16, true);
        cpcommit();
    }
    const int NCH = KDIM / 32;
    for (int ch = 0; ch < NCH; ch++) {
        int cur = ch & 1;
        if (ch + 1 < NCH) {
            int nb = cur ^ 1;
            uint32_t as = smB + aOff[nb] + (uint32_t)(ar * AST) * 4 + aSeg;
            const char* ag = aG + (ch + 1) * 64;
            cp16(as, ag, true); cp16(as + 16, ag + 16, true);
            uint32_t bs = smB + bOff[nb] + (uint32_t)(bRow * AST) * 4 + bSeg;
            const char* bg = bG + (ch + 1) * 64;
            #pragma unroll
            for (int s = 0; s < SEG / 16; s++) cp16(bs + s * 16, bg + s * 16, true);
            cpcommit(); cpwait<1>();
        } else cpwait<0>();
        __syncthreads();
        uint32_t aT = smB + aOff[cur] + aLd;
        uint32_t bT = smB + bOff[cur] + bLd;
        #pragma unroll
        for (int ks = 0; ks < 2; ks++) {
            uint32_t a[2][4], b[NJ][2];
            #pragma unroll
            for (int mi = 0; mi < 2; mi++)
                ldsm4(a[mi], aT + (uint32_t)(mi * 16 * AST + ks * 8) * 4);
            #pragma unroll
            for (int p = 0; p < NJ / 2; p++) {
                uint32_t r[4];
                ldsm4(r, bT + (uint32_t)(p * 16 * AST + ks * 8) * 4);
                b[2 * p][0] = r[0]; b[2 * p][1] = r[1];
                b[2 * p + 1][0] = r[2]; b[2 * p + 1][1] = r[3];
            }
            #pragma unroll
            for (int mi = 0; mi < 2; mi++)
                #pragma unroll
                for (int nj = 0; nj < NJ; nj++)
                    mma_bf16(c[mi][nj], a[mi], b[nj]);
        }
        __syncthreads();
    }
    #pragma unroll
    for (int mi = 0; mi < 2; mi++) {
        #pragma unroll
        for (int nj = 0; nj < NJ; nj++) {
            int r0 = row0 + wm + mi * 16 + grp;
            int col = nc + wn + nj * 8 + 2 * qid;
            long o0 = (long)r0 * NOUT + col;
            long o1 = (long)(r0 + 8) * NOUT + col;
            *reinterpret_cast<float2*>(&P[o0]) = make_float2(c[mi][nj][0], c[mi][nj][1]);
            *reinterpret_cast<float2*>(&P[o1]) = make_float2(c[mi][nj][2], c[mi][nj][3]);
            *reinterpret_cast<__nv_bfloat162*>(&Ph[o0]) =
                __floats2bfloat162_rn(c[mi][nj][0], c[mi][nj][1]);
            *reinterpret_cast<__nv_bfloat162*>(&Ph[o1]) =
                __floats2bfloat162_rn(c[mi][nj][2], c[mi][nj][3]);
        }
    }
}

__global__ void __launch_bounds__(256) proj_all() {
    extern __shared__ uint32_t smp[];
    if (blockIdx.y < 2) proj_body<D0, 128, 0>(smp, blockIdx.y);
    else                proj_body<D1, 64, 1>(smp, 0);
}

// =============== merged bf16 exp-sum, warp tile m64n32, 2 CTA/SM =============
// chunked (CH=64, ST=36): A[2][256*36=9216] | B[2][64*36=2304] @18432 | rowAcc @23040
// resident tail1:          A[256*36=9216]    | B[2][64*36]      @9216  | rowAcc @13824
#define SM_EXP_U32 23552

// ---- chunked body (head MODE 0 / tail0 MODE 1); N-tile 64, k-chunk 64 -------
template<int K, int MODE>
__device__ __forceinline__ void chunked_body(uint32_t* sm, int yIdx) {
    const int ST = 36;
    float* rowAcc = (float*)(sm + 23040);
    uint32_t smB = (uint32_t)__cvta_generic_to_shared(sm);
    const uint32_t aOff[2] = { 0u, 9216u * 4 };
    const uint32_t bOff[2] = { 18432u * 4, 20736u * 4 };

    int M, ncols;
    const __nv_bfloat16 *Asrc, *Bsrc;
    float* sums;
    if (MODE == 0) { M = NROWS; ncols = NHEAD; Asrc = g_inh;    Bsrc = g_headWh; sums = g_sum_head; }
    else           { M = g_cnt0; ncols = SZ0;  Asrc = g_proj0h; Bsrc = g_emb0h;  sums = g_sum_tail; }

    int row0 = blockIdx.x * 256;
    if (row0 >= M) return;
    int tid = threadIdx.x;
    int rid = row0 + tid; if (rid > M - 1) rid = M - 1;
    int myRow = (MODE == 0) ? rid : g_idx0[rid];
    rowAcc[tid] = 0.f;

    int warp = tid >> 5, lane = tid & 31, grp = lane >> 2, qid = lane & 3;
    int wm = (warp >> 1) * 64, wn = (warp & 1) * 32;
    int nc = yIdx * 64;

    const char* aG = (const char*)(Asrc + (size_t)myRow * K);
    int bRow = tid >> 2, bSeg = (tid & 3) * 32;
    int bGRow = nc + bRow;
    bool bv = bGRow < ncols;
    const char* bG = (const char*)(Bsrc + (size_t)(bv ? bGRow : 0) * K);

    uint32_t aLd = (uint32_t)((wm + (lane & 15)) * ST + (lane >> 4) * 4) * 4;
    uint32_t bLd = (uint32_t)((wn + ((lane >> 4) & 1) * 8 + (lane & 7)) * ST
                              + ((lane >> 3) & 1) * 4) * 4;

    float c[4][4][4];
    #pragma unroll
    for (int mi = 0; mi < 4; mi++)
        #pragma unroll
        for (int nj = 0; nj < 4; nj++)
            #pragma unroll
            for (int r = 0; r < 4; r++) c[mi][nj][r] = 0.f;

    {   // chunk 0
        uint32_t as = smB + aOff[0] + (uint32_t)tid * ST * 4;
        #pragma unroll
        for (int s = 0; s < 8; s++) cp16(as + s * 16, aG + s * 16, true);
        uint32_t bs = smB + bOff[0] + (uint32_t)bRow * ST * 4 + bSeg;
        cp16(bs, bG + bSeg, bv); cp16(bs + 16, bG + bSeg + 16, bv);
        cpcommit();
    }
    const int NCH = K / 64;
    for (int ch = 0; ch < NCH; ch++) {
        int cur = ch & 1;
        if (ch + 1 < NCH) {
            int nb = cur ^ 1;
            uint32_t as = smB + aOff[nb] + (uint32_t)tid * ST * 4;
            const char* ag = aG + (ch + 1) * 128;
            #pragma unroll
            for (int s = 0; s < 8; s++) cp16(as + s * 16, ag + s * 16, true);
            uint32_t bs = smB + bOff[nb] + (uint32_t)bRow * ST * 4 + bSeg;
            const char* bg = bG + (ch + 1) * 128 + bSeg;
            cp16(bs, bg, bv); cp16(bs + 16, bg + 16, bv);
            cpcommit(); cpwait<1>();
        } else cpwait<0>();
        __syncthreads();
        uint32_t aT = smB + aOff[cur] + aLd;
        uint32_t bT = smB + bOff[cur] + bLd;
        #pragma unroll
        for (int ks = 0; ks < 4; ks++) {
            uint32_t a[4][4], b[4][2];
            #pragma unroll
            for (int mi = 0; mi < 4; mi++)
                ldsm4(a[mi], aT + (uint32_t)(mi * 16 * ST + ks * 8) * 4);
            #pragma unroll
            for (int p = 0; p < 2; p++) {
                uint32_t r[4];
                ldsm4(r, bT + (uint32_t)(p * 16 * ST + ks * 8) * 4);
                b[2 * p][0] = r[0]; b[2 * p][1] = r[1];
                b[2 * p + 1][0] = r[2]; b[2 * p + 1][1] = r[3];
            }
            #pragma unroll
            for (int mi = 0; mi < 4; mi++)
                #pragma unroll
                for (int nj = 0; nj < 4; nj++)
                    mma_bf16(c[mi][nj], a[mi], b[nj]);
        }
        __syncthreads();
    }
    #pragma unroll
    for (int mi = 0; mi < 4; mi++) {
        float s0 = 0.f, s1 = 0.f;
        #pragma unroll
        for (int nj = 0; nj < 4; nj++) {
            int col = nc + wn + nj * 8 + 2 * qid;
            if (col < ncols)     { s0 += ex2f(c[mi][nj][0]); s1 += ex2f(c[mi][nj][2]); }
            if (col + 1 < ncols) { s0 += ex2f(c[mi][nj][1]); s1 += ex2f(c[mi][nj][3]); }
        }
        s0 += __shfl_xor_sync(0xffffffffu, s0, 1);
        s0 += __shfl_xor_sync(0xffffffffu, s0, 2);
        s1 += __shfl_xor_sync(0xffffffffu, s1, 1);
        s1 += __shfl_xor_sync(0xffffffffu, s1, 2);
        if (qid == 0) {
            atomicAdd(&rowAcc[wm + mi * 16 + grp], s0);
            atomicAdd(&rowAcc[wm + mi * 16 + grp + 8], s1);
        }
    }
    __syncthreads();
    if (row0 + tid < M) atomicAdd(&sums[myRow], rowAcc[tid]);
}

// ---- tail1 resident body: K=64, A in smem once, B double-buffered;
//      REGISTER row-accumulation across tiles (single combine at end) --------
template<int NUMY>
__device__ __forceinline__ void tail1_body(uint32_t* sm, int yIdx) {
    const int K = 64, ST = 36;
    float* rowAcc = (float*)(sm + 9216 + 4608);
    uint32_t smB = (uint32_t)__cvta_generic_to_shared(sm);
    const uint32_t bOff[2] = { 9216u * 4, (9216u + 2304u) * 4 };

    int M = g_cnt1;
    int ncols = SZ1;
    int row0 = blockIdx.x * 256;
    if (row0 >= M) return;
    int tid = threadIdx.x;
    int rid = row0 + tid; if (rid > M - 1) rid = M - 1;
    int myRow = g_idx1[rid];
    rowAcc[tid] = 0.f;

    {
        const char* aG = (const char*)(g_proj1h + (size_t)myRow * K);
        uint32_t as = smB + (uint32_t)tid * ST * 4;
        #pragma unroll
        for (int s = 0; s < 8; s++) cp16(as + s * 16, aG + s * 16, true);
    }
    int bRow = tid >> 2, bSeg = (tid & 3) * 32;
    int warp = tid >> 5, lane = tid & 31, grp = lane >> 2, qid = lane & 3;
    int wm = (warp >> 1) * 64, wn = (warp & 1) * 32;

    uint32_t aLd = (uint32_t)((wm + (lane & 15)) * ST + (lane >> 4) * 4) * 4;
    uint32_t bLd = (uint32_t)((wn + ((lane >> 4) & 1) * 8 + (lane & 7)) * ST
                              + ((lane >> 3) & 1) * 4) * 4;

    int ncStride = NUMY * 64;
    int nc0 = yIdx * 64;

    auto loadB = [&](int nc, int buf) {
        int br = nc + bRow;
        bool v = br < ncols;
        const char* bg = (const char*)(g_emb1h + (size_t)(v ? br : 0) * K) + bSeg;
        uint32_t bs = smB + bOff[buf] + (uint32_t)bRow * ST * 4 + bSeg;
        cp16(bs, bg, v); cp16(bs + 16, bg + 16, v);
    };
    if (nc0 < ncols) loadB(nc0, 0);
    cpcommit();

    float racc[4][2];
    #pragma unroll
    for (int mi = 0; mi < 4; mi++) { racc[mi][0] = 0.f; racc[mi][1] = 0.f; }

    int buf = 0;
    for (int nc = nc0; nc < ncols; nc += ncStride) {
        if (nc + ncStride < ncols) { loadB(nc + ncStride, buf ^ 1); cpcommit(); cpwait<1>(); }
        else cpwait<0>();
        __syncthreads();

        float c[4][4][4];
        #pragma unroll
        for (int mi = 0; mi < 4; mi++)
            #pragma unroll
            for (int nj = 0; nj < 4; nj++)
                #pragma unroll
                for (int r = 0; r < 4; r++) c[mi][nj][r] = 0.f;

        uint32_t aT = smB + aLd;
        uint32_t bT = smB + bOff[buf] + bLd;
        #pragma unroll
        for (int ks = 0; ks < 4; ks++) {
            uint32_t a[4][4], b[4][2];
            #pragma unroll
            for (int mi = 0; mi < 4; mi++)
                ldsm4(a[mi], aT + (uint32_t)(mi * 16 * ST + ks * 8) * 4);
            #pragma unroll
            for (int p = 0; p < 2; p++) {
                uint32_t r[4];
                ldsm4(r, bT + (uint32_t)(p * 16 * ST + ks * 8) * 4);
                b[2 * p][0] = r[0]; b[2 * p][1] = r[1];
                b[2 * p + 1][0] = r[2]; b[2 * p + 1][1] = r[3];
            }
            #pragma unroll
            for (int mi = 0; mi < 4; mi++)
                #pragma unroll
                for (int nj = 0; nj < 4; nj++)
                    mma_bf16(c[mi][nj], a[mi], b[nj]);
        }
        // register accumulation (fast full-tile path; masked on edge tile)
        if (nc + 64 <= ncols) {
            #pragma unroll
            for (int mi = 0; mi < 4; mi++) {
                #pragma unroll
                for (int nj = 0; nj < 4; nj++) {
                    racc[mi][0] += ex2f(c[mi][nj][0]) + ex2f(c[mi][nj][1]);
                    racc[mi][1] += ex2f(c[mi][nj][2]) + ex2f(c[mi][nj][3]);
                }
            }
        } else {
            #pragma unroll
            for (int mi = 0; mi < 4; mi++) {
                #pragma unroll
                for (int nj = 0; nj < 4; nj++) {
                    int col = nc + wn + nj * 8 + 2 * qid;
                    if (col < ncols)     { racc[mi][0] += ex2f(c[mi][nj][0]); racc[mi][1] += ex2f(c[mi][nj][2]); }
                    if (col + 1 < ncols) { racc[mi][0] += ex2f(c[mi][nj][1]); racc[mi][1] += ex2f(c[mi][nj][3]); }
                }
            }
        }
        __syncthreads();
        buf ^= 1;
    }
    // single combine
    #pragma unroll
    for (int mi = 0; mi < 4; mi++) {
        float s0 = racc[mi][0], s1 = racc[mi][1];
        s0 += __shfl_xor_sync(0xffffffffu, s0, 1);
        s0 += __shfl_xor_sync(0xffffffffu, s0, 2);
        s1 += __shfl_xor_sync(0xffffffffu, s1, 1);
        s1 += __shfl_xor_sync(0xffffffffu, s1, 2);
        if (qid == 0) {
            atomicAdd(&rowAcc[wm + mi * 16 + grp], s0);
            atomicAdd(&rowAcc[wm + mi * 16 + grp + 8], s1);
        }
    }
    __syncthreads();
    if (row0 + tid < M) atomicAdd(&g_sum_tail[myRow], rowAcc[tid]);
}

// y-map: [0,32) head tiles | [32,72) tail1 partitions | [72,197) tail0 tiles
__global__ void __launch_bounds__(256, 2) expsum_all() {
    extern __shared__ uint32_t sm[];
    if (blockIdx.y < 32)      chunked_body<KDIM, 0>(sm, blockIdx.y);
    else if (blockIdx.y < 72) tail1_body<40>(sm, blockIdx.y - 32);
    else                      chunked_body<D0, 1>(sm, blockIdx.y - 72);
}

// ---------------- final gather ----------------------------------------------
__global__ void __launch_bounds__(256) final_kernel(
    const float* __restrict__ inputs, const int* __restrict__ targets,
    const float* __restrict__ head_W, const float* __restrict__ emb0,
    const float* __restrict__ emb1, float* __restrict__ out)
{
    int warp = (blockIdx.x * blockDim.x + threadIdx.x) >> 5;
    int lane = threadIdx.x & 31;
    if (warp >= NROWS) return;
    int row = warp;
    int t = targets[row];
    int ht = (t < CUT0) ? t : ((t < CUT1) ? CUT0 : CUT0 + 1);

    float s = 0.f;
    const float* x = inputs + (long)row * KDIM;
    const float* w = head_W + (long)ht * KDIM;
    for (int k = lane; k < KDIM; k += 32) s += x[k] * w[k];
    #pragma unroll
    for (int o = 16; o; o >>= 1) s += __shfl_xor_sync(0xffffffffu, s, o);
    float res = s - logf(g_sum_head[row]);

    if (t >= CUT0) {
        float tl = 0.f;
        if (t < CUT1) {
            const float* p = g_proj0 + (long)row * D0;
            const float* e = emb0 + (long)(t - CUT0) * D0;
            for (int k = lane; k < D0; k += 32) tl += p[k] * e[k];
        } else {
            const float* p = g_proj1 + (long)row * D1;
            const float* e = emb1 + (long)(t - CUT1) * D1;
            for (int k = lane; k < D1; k += 32) tl += p[k] * e[k];
        }
        #pragma unroll
        for (int o = 16; o; o >>= 1) tl += __shfl_xor_sync(0xffffffffu, tl, o);
        res += tl - logf(g_sum_tail[row]);
    }
    if (lane == 0) out[row] = res;
}

// -------- loss reduction (double) + state reset for next replay ---------------
__global__ void __launch_bounds__(1024) loss_kernel(float* __restrict__ out, int out_size) {
    __shared__ double sh[1024];
    int tid = threadIdx.x;
    double s = 0.0;
    for (int i = tid; i < NROWS; i += 1024) s += (double)out[i];
    sh[tid] = s;
    __syncthreads();
    for (int o = 512; o; o >>= 1) {
        if (tid < o) sh[tid] += sh[tid + o];
        __syncthreads();
    }
    if (tid == 0 && out_size > NROWS)
        out[out_size - 1] = (float)(-sh[0] / (double)NROWS);
    for (int i = tid; i < NROWS; i += 1024) { g_sum_head[i] = 0.f; g_sum_tail[i] = 0.f; }
    if (tid == 0) { g_cnt0 = 0; g_cnt1 = 0; }
}

// ---------------- launch -----------------------------------------------------
extern "C" void kernel_launch(void* const* d_in, const int* in_sizes, int n_in,
                              void* d_out, int out_size) {
    const float* inputs = 0; const int* targets = 0; const float* head_W = 0;
    const float* emb0 = 0; const float* lin0 = 0; const float* emb1 = 0; const float* lin1 = 0;
    for (int i = 0; i < n_in; i++) {
        switch (in_sizes[i]) {
            case NROWS * KDIM:  inputs  = (const float*)d_in[i]; break;
            case NROWS:         targets = (const int*)  d_in[i]; break;
            case NHEAD * KDIM:  head_W  = (const float*)d_in[i]; break;
            case SZ0 * D0:      emb0    = (const float*)d_in[i]; break;
            case KDIM * D0:     lin0    = (const float*)d_in[i]; break;
            case SZ1 * D1:      emb1    = (const float*)d_in[i]; break;
            case KDIM * D1:     lin1    = (const float*)d_in[i]; break;
        }
    }
    float* out = (float*)d_out;

    const int SMEM_PROJ = (2 * 2560 + 2 * 128 * 20) * 4;    // 40 KB
    const int SMEM_EXP  = SM_EXP_U32 * 4;                   // 94.2 KB (2 CTA/SM)
    cudaFuncSetAttribute(proj_all,   cudaFuncAttributeMaxDynamicSharedMemorySize, SMEM_PROJ);
    cudaFuncSetAttribute(expsum_all, cudaFuncAttributeMaxDynamicSharedMemorySize, SMEM_EXP);

    prep_kernel<<<2048, 256>>>(inputs, head_W, emb0, emb1, lin0, lin1, targets);
    proj_all<<<dim3(32, 3), 256, SMEM_PROJ>>>();
    expsum_all<<<dim3(16, 197), 256, SMEM_EXP>>>();
    final_kernel<<<(NROWS * 32) / 256, 256>>>(inputs, targets, head_W, emb0, emb1, out);
    loss_kernel<<<1, 1024>>>(out, out_size);
}